// round 3
// baseline (speedup 1.0000x reference)
#include <cuda_runtime.h>
#include <math.h>

#define DM 512
#define NH 8
#define DH 64
#define LQn 2048
#define LKn 4096
#define BSZ 2

#define BQ 64
#define BK 32

// Scratch (allocation-free): projected Q/K/V and attention output, all fp32.
__device__ float g_Qp[(size_t)BSZ * LQn * DM];   // [B*LQ, DM]
__device__ float g_Kp[(size_t)BSZ * LKn * DM];   // [B*LK, DM]
__device__ float g_Vp[(size_t)BSZ * LKn * DM];   // [B*LK, DM]
__device__ float g_AO[(size_t)BSZ * LQn * DM];   // [B*LQ, DM] attention out (heads concat)

// C[M,N] = A[M,K] @ W[N,K]^T + bias[N]
// 64x64 block tile, 16x16 threads, 4x4 micro-tile, BK=16.
__global__ void gemm_bias_kernel(const float* __restrict__ A,
                                 const float* __restrict__ W,
                                 const float* __restrict__ bias,
                                 float* __restrict__ C,
                                 int M, int N, int K) {
    __shared__ float As[16][64];
    __shared__ float Ws[16][64];
    int tid = threadIdx.x;
    int tx = tid & 15, ty = tid >> 4;
    int n0 = blockIdx.x * 64, m0 = blockIdx.y * 64;

    float acc[4][4] = {};

    for (int k0 = 0; k0 < K; k0 += 16) {
        #pragma unroll
        for (int t = 0; t < 4; t++) {
            int idx = tid + t * 256;
            int r = idx >> 4, c = idx & 15;
            As[c][r] = A[(size_t)(m0 + r) * K + k0 + c];
            Ws[c][r] = W[(size_t)(n0 + r) * K + k0 + c];
        }
        __syncthreads();
        #pragma unroll
        for (int k = 0; k < 16; k++) {
            float a[4], b[4];
            #pragma unroll
            for (int i = 0; i < 4; i++) a[i] = As[k][ty * 4 + i];
            #pragma unroll
            for (int j = 0; j < 4; j++) b[j] = Ws[k][tx * 4 + j];
            #pragma unroll
            for (int i = 0; i < 4; i++)
                #pragma unroll
                for (int j = 0; j < 4; j++)
                    acc[i][j] = fmaf(a[i], b[j], acc[i][j]);
        }
        __syncthreads();
    }

    #pragma unroll
    for (int i = 0; i < 4; i++) {
        int m = m0 + ty * 4 + i;
        #pragma unroll
        for (int j = 0; j < 4; j++) {
            int n = n0 + tx * 4 + j;
            C[(size_t)m * N + n] = acc[i][j] + bias[n];
        }
    }
}

// Flash-attention over one (b, h, q-tile): online softmax with gate + mask.
// 256 threads. Scores: 64q x 32k tile (4x2 micro). O accum: 64q x 64d (4x4 micro).
__global__ void attn_kernel(const float* __restrict__ gate,
                            const int* __restrict__ mask) {
    __shared__ float Qs[BQ][DH];        // 16 KB
    __shared__ float KVs[BK][DH + 1];   // 8.3 KB (K tile, then reused as V tile)
    __shared__ float Ss[BQ][BK + 1];    // 8.4 KB
    __shared__ float row_alpha[BQ];
    __shared__ float gsm[BK];

    int q0 = blockIdx.x * BQ;
    int h = blockIdx.y, b = blockIdx.z;
    int tid = threadIdx.x;
    int tx = tid & 15, ty = tid >> 4;

    const float* Qbase = g_Qp + ((size_t)b * LQn) * DM + h * DH;
    const float* Kbase = g_Kp + ((size_t)b * LKn) * DM + h * DH;
    const float* Vbase = g_Vp + ((size_t)b * LKn) * DM + h * DH;
    const float* gb = gate + (size_t)b * LKn;
    const int* mb = mask + (size_t)b * LKn;

    // Load Q tile (vectorized)
    for (int i = tid; i < BQ * DH / 4; i += 256) {
        int r = i >> 4;
        int c4 = (i & 15) * 4;
        float4 v = *(const float4*)(Qbase + (size_t)(q0 + r) * DM + c4);
        *(float4*)&Qs[r][c4] = v;
    }

    float m_i = -1e30f, l_i = 0.0f;   // meaningful for tid < 64 (row = tid)
    float acc[4][4] = {};
    __syncthreads();

    for (int k0 = 0; k0 < LKn; k0 += BK) {
        // Load K tile
        for (int i = tid; i < BK * DH; i += 256) {
            int r = i >> 6, c = i & 63;
            KVs[r][c] = Kbase[(size_t)(k0 + r) * DM + c];
        }
        if (tid < BK) {
            float g = logf(fmaxf(gb[k0 + tid], 1e-6f));
            gsm[tid] = (mb[k0 + tid] == 0) ? -1e30f : g;
        }
        __syncthreads();

        // S = Q @ K^T * scale + gate/mask  (rows ty*4+i, cols tx*2+j)
        float s[4][2] = {};
        #pragma unroll
        for (int d = 0; d < DH; d++) {
            float a[4], kk[2];
            #pragma unroll
            for (int i = 0; i < 4; i++) a[i] = Qs[ty * 4 + i][d];
            #pragma unroll
            for (int j = 0; j < 2; j++) kk[j] = KVs[tx * 2 + j][d];
            #pragma unroll
            for (int i = 0; i < 4; i++)
                #pragma unroll
                for (int j = 0; j < 2; j++)
                    s[i][j] = fmaf(a[i], kk[j], s[i][j]);
        }
        #pragma unroll
        for (int i = 0; i < 4; i++)
            #pragma unroll
            for (int j = 0; j < 2; j++) {
                int col = tx * 2 + j;
                Ss[ty * 4 + i][col] = s[i][j] * 0.125f + gsm[col];
            }
        __syncthreads();

        // Online softmax per row (threads 0..63), others start loading V.
        if (tid < BQ) {
            float mx = m_i;
            #pragma unroll
            for (int j = 0; j < BK; j++) mx = fmaxf(mx, Ss[tid][j]);
            float alpha = __expf(m_i - mx);
            float sum = 0.0f;
            #pragma unroll
            for (int j = 0; j < BK; j++) {
                float p = __expf(Ss[tid][j] - mx);
                Ss[tid][j] = p;
                sum += p;
            }
            l_i = l_i * alpha + sum;
            m_i = mx;
            row_alpha[tid] = alpha;
        }
        // Load V tile into KVs (safe: all KVs reads finished before prior sync)
        for (int i = tid; i < BK * DH; i += 256) {
            int r = i >> 6, c = i & 63;
            KVs[r][c] = Vbase[(size_t)(k0 + r) * DM + c];
        }
        __syncthreads();

        // Rescale accumulators, then O += P @ V
        #pragma unroll
        for (int i = 0; i < 4; i++) {
            float al = row_alpha[ty * 4 + i];
            #pragma unroll
            for (int j = 0; j < 4; j++) acc[i][j] *= al;
        }
        #pragma unroll
        for (int k = 0; k < BK; k++) {
            float p[4], v[4];
            #pragma unroll
            for (int i = 0; i < 4; i++) p[i] = Ss[ty * 4 + i][k];
            #pragma unroll
            for (int j = 0; j < 4; j++) v[j] = KVs[k][tx * 4 + j];
            #pragma unroll
            for (int i = 0; i < 4; i++)
                #pragma unroll
                for (int j = 0; j < 4; j++)
                    acc[i][j] = fmaf(p[i], v[j], acc[i][j]);
        }
        __syncthreads();
    }

    if (tid < BQ) row_alpha[tid] = 1.0f / l_i;
    __syncthreads();

    float* Obase = g_AO + ((size_t)b * LQn + q0) * DM + h * DH;
    #pragma unroll
    for (int i = 0; i < 4; i++) {
        float inv = row_alpha[ty * 4 + i];
        #pragma unroll
        for (int j = 0; j < 4; j++)
            Obase[(size_t)(ty * 4 + i) * DM + tx * 4 + j] = acc[i][j] * inv;
    }
}

extern "C" void kernel_launch(void* const* d_in, const int* in_sizes, int n_in,
                              void* d_out, int out_size) {
    const float* q    = (const float*)d_in[0];
    const float* kv   = (const float*)d_in[1];
    const float* gate = (const float*)d_in[2];
    const int*   mask = (const int*)d_in[3];
    const float* Wq   = (const float*)d_in[4];
    const float* bq   = (const float*)d_in[5];
    const float* Wk   = (const float*)d_in[6];
    const float* bk   = (const float*)d_in[7];
    const float* Wv   = (const float*)d_in[8];
    const float* bv   = (const float*)d_in[9];
    const float* Wo   = (const float*)d_in[10];
    const float* bo   = (const float*)d_in[11];
    float* out = (float*)d_out;

    float *Qp, *Kp, *Vp, *AO;
    cudaGetSymbolAddress((void**)&Qp, g_Qp);
    cudaGetSymbolAddress((void**)&Kp, g_Kp);
    cudaGetSymbolAddress((void**)&Vp, g_Vp);
    cudaGetSymbolAddress((void**)&AO, g_AO);

    dim3 thr(256);
    // Projections
    gemm_bias_kernel<<<dim3(DM / 64, (BSZ * LQn) / 64), thr>>>(q,  Wq, bq, Qp, BSZ * LQn, DM, DM);
    gemm_bias_kernel<<<dim3(DM / 64, (BSZ * LKn) / 64), thr>>>(kv, Wk, bk, Kp, BSZ * LKn, DM, DM);
    gemm_bias_kernel<<<dim3(DM / 64, (BSZ * LKn) / 64), thr>>>(kv, Wv, bv, Vp, BSZ * LKn, DM, DM);
    // Attention
    attn_kernel<<<dim3(LQn / BQ, NH, BSZ), thr>>>(gate, mask);
    // Output projection
    gemm_bias_kernel<<<dim3(DM / 64, (BSZ * LQn) / 64), thr>>>(AO, Wo, bo, out, BSZ * LQn, DM, DM);
}

// round 5
// speedup vs baseline: 1.7575x; 1.7575x over previous
#include <cuda_runtime.h>
#include <cuda_bf16.h>
#include <math.h>
#include <stdint.h>

#define DM 512
#define NH 8
#define DH 64
#define LQn 2048
#define LKn 4096
#define BSZ 2

#define BQ 64
#define BK 64

// Scratch (allocation-free): projected Q/K/V and attention output, all fp32.
__device__ float g_Qp[(size_t)BSZ * LQn * DM];   // [B*LQ, DM]
__device__ float g_Kp[(size_t)BSZ * LKn * DM];   // [B*LK, DM]
__device__ float g_Vp[(size_t)BSZ * LKn * DM];   // [B*LK, DM]
__device__ float g_AO[(size_t)BSZ * LQn * DM];   // [B*LQ, DM] attention out (heads concat)

// ---------------------------------------------------------------------------
// GEMM: C[M,N] = A[M,K] @ W[N,K]^T + bias[N]  (unchanged from baseline)
// ---------------------------------------------------------------------------
__global__ void gemm_bias_kernel(const float* __restrict__ A,
                                 const float* __restrict__ W,
                                 const float* __restrict__ bias,
                                 float* __restrict__ C,
                                 int M, int N, int K) {
    __shared__ float As[16][64];
    __shared__ float Ws[16][64];
    int tid = threadIdx.x;
    int tx = tid & 15, ty = tid >> 4;
    int n0 = blockIdx.x * 64, m0 = blockIdx.y * 64;

    float acc[4][4] = {};

    for (int k0 = 0; k0 < K; k0 += 16) {
        #pragma unroll
        for (int t = 0; t < 4; t++) {
            int idx = tid + t * 256;
            int r = idx >> 4, c = idx & 15;
            As[c][r] = A[(size_t)(m0 + r) * K + k0 + c];
            Ws[c][r] = W[(size_t)(n0 + r) * K + k0 + c];
        }
        __syncthreads();
        #pragma unroll
        for (int k = 0; k < 16; k++) {
            float a[4], b[4];
            #pragma unroll
            for (int i = 0; i < 4; i++) a[i] = As[k][ty * 4 + i];
            #pragma unroll
            for (int j = 0; j < 4; j++) b[j] = Ws[k][tx * 4 + j];
            #pragma unroll
            for (int i = 0; i < 4; i++)
                #pragma unroll
                for (int j = 0; j < 4; j++)
                    acc[i][j] = fmaf(a[i], b[j], acc[i][j]);
        }
        __syncthreads();
    }

    #pragma unroll
    for (int i = 0; i < 4; i++) {
        int m = m0 + ty * 4 + i;
        #pragma unroll
        for (int j = 0; j < 4; j++) {
            int n = n0 + tx * 4 + j;
            C[(size_t)m * N + n] = acc[i][j] + bias[n];
        }
    }
}

// ---------------------------------------------------------------------------
// Tensor-core flash attention.
//   4 warps / CTA, each warp owns 16 q-rows (full BK=64 key tile, full DH=64).
//   S = Q K^T : mma.m16n8k8.tf32 (scale folded into Q; gate+mask added after)
//   P V      : mma.m16n8k16.bf16, 3-term hi/lo split for full fp32-grade accuracy
//   P stays in registers: S C-fragment layout == PV A-fragment layout.
// ---------------------------------------------------------------------------

__device__ __forceinline__ void mma_tf32(float c[4], const uint32_t a[4],
                                         uint32_t b0, uint32_t b1) {
    asm volatile(
        "mma.sync.aligned.m16n8k8.row.col.f32.tf32.tf32.f32 "
        "{%0,%1,%2,%3}, {%4,%5,%6,%7}, {%8,%9}, {%0,%1,%2,%3};"
        : "+f"(c[0]), "+f"(c[1]), "+f"(c[2]), "+f"(c[3])
        : "r"(a[0]), "r"(a[1]), "r"(a[2]), "r"(a[3]), "r"(b0), "r"(b1));
}

__device__ __forceinline__ void mma_bf16(float c[4], const uint32_t a[4],
                                         uint32_t b0, uint32_t b1) {
    asm volatile(
        "mma.sync.aligned.m16n8k16.row.col.f32.bf16.bf16.f32 "
        "{%0,%1,%2,%3}, {%4,%5,%6,%7}, {%8,%9}, {%0,%1,%2,%3};"
        : "+f"(c[0]), "+f"(c[1]), "+f"(c[2]), "+f"(c[3])
        : "r"(a[0]), "r"(a[1]), "r"(a[2]), "r"(a[3]), "r"(b0), "r"(b1));
}

__device__ __forceinline__ uint32_t cvt_tf32(float f) {
    uint32_t u;
    asm("cvt.rna.tf32.f32 %0, %1;" : "=r"(u) : "f"(f));
    return u;
}

// pack (f0 -> low half, f1 -> high half) as bf16x2, and the bf16 residual pair
__device__ __forceinline__ void pack_bf16_hilo(float f0, float f1,
                                               uint32_t& hi, uint32_t& lo) {
    asm("cvt.rn.bf16x2.f32 %0, %1, %2;" : "=r"(hi) : "f"(f1), "f"(f0));
    float h0 = __uint_as_float(hi << 16);
    float h1 = __uint_as_float(hi & 0xffff0000u);
    float r0 = f0 - h0, r1 = f1 - h1;
    asm("cvt.rn.bf16x2.f32 %0, %1, %2;" : "=r"(lo) : "f"(r1), "f"(r0));
}

#define KS_STRIDE 68           // fp32 words per row (64 + 4 pad) -> conflict-free
#define VT_STRIDE 72           // bf16 elems per row (64 + 8 pad) -> conflict-free

__global__ __launch_bounds__(128, 2)
void attn_kernel(const float* __restrict__ gate, const int* __restrict__ mask) {
    __shared__ uint32_t Ks[BK * KS_STRIDE];              // K tile, tf32 bits (also Q staging)
    __shared__ __nv_bfloat16 VtHi[DH * VT_STRIDE];       // V^T hi, [d][key]
    __shared__ __nv_bfloat16 VtLo[DH * VT_STRIDE];       // V^T lo
    __shared__ float gsm[BK];

    const int tid = threadIdx.x;
    const int lane = tid & 31, warp = tid >> 5;
    const int qr = lane >> 2;       // 0..7  (row-in-16 group)
    const int qc = lane & 3;        // 0..3  (col group)
    const int r0 = warp * 16;       // warp's q-row base within tile

    const int q0 = blockIdx.x * BQ;
    const int h = blockIdx.y, b = blockIdx.z;

    const float* Qb = g_Qp + ((size_t)b * LQn + q0) * DM + h * DH;
    const float* Kb = g_Kp + (size_t)b * LKn * DM + h * DH;
    const float* Vb = g_Vp + (size_t)b * LKn * DM + h * DH;
    const float* gb = gate + (size_t)b * LKn;
    const int*   mb = mask + (size_t)b * LKn;

    // ---- Stage Q tile into Ks (scaled by 1/8, tf32-rounded), extract A frags ----
    #pragma unroll
    for (int p = 0; p < 8; p++) {
        int idx = tid + p * 128;
        int r = idx >> 4, cg = (idx & 15) << 2;
        float4 v = *(const float4*)(Qb + (size_t)r * DM + cg);
        uint4 u;
        u.x = cvt_tf32(v.x * 0.125f);
        u.y = cvt_tf32(v.y * 0.125f);
        u.z = cvt_tf32(v.z * 0.125f);
        u.w = cvt_tf32(v.w * 0.125f);
        *(uint4*)&Ks[r * KS_STRIDE + cg] = u;
    }
    __syncthreads();

    uint32_t qa[8][4];   // Q A-fragments, persistent for the whole kernel
    #pragma unroll
    for (int kb = 0; kb < 8; kb++) {
        qa[kb][0] = Ks[(r0 + qr) * KS_STRIDE + 8 * kb + qc];
        qa[kb][1] = Ks[(r0 + qr + 8) * KS_STRIDE + 8 * kb + qc];
        qa[kb][2] = Ks[(r0 + qr) * KS_STRIDE + 8 * kb + qc + 4];
        qa[kb][3] = Ks[(r0 + qr + 8) * KS_STRIDE + 8 * kb + qc + 4];
    }
    __syncthreads();

    float m_a = -1e30f, m_b = -1e30f, l_a = 0.0f, l_b = 0.0f;
    float oacc[8][4];
    #pragma unroll
    for (int nb = 0; nb < 8; nb++)
        #pragma unroll
        for (int i = 0; i < 4; i++) oacc[nb][i] = 0.0f;

    for (int k0 = 0; k0 < LKn; k0 += BK) {
        // ---- Load K tile (tf32 bits, padded) ----
        #pragma unroll
        for (int p = 0; p < 8; p++) {
            int idx = tid + p * 128;
            int r = idx >> 4, cg = (idx & 15) << 2;
            float4 v = *(const float4*)(Kb + (size_t)(k0 + r) * DM + cg);
            uint4 u;
            u.x = cvt_tf32(v.x); u.y = cvt_tf32(v.y);
            u.z = cvt_tf32(v.z); u.w = cvt_tf32(v.w);
            *(uint4*)&Ks[r * KS_STRIDE + cg] = u;
        }
        // ---- Load V tile, transpose to [d][key], split bf16 hi/lo ----
        #pragma unroll
        for (int p = 0; p < 8; p++) {
            int idx = tid + p * 128;
            int key = idx >> 4, dg = (idx & 15) << 2;
            float4 v = *(const float4*)(Vb + (size_t)(k0 + key) * DM + dg);
            float f[4] = {v.x, v.y, v.z, v.w};
            #pragma unroll
            for (int j = 0; j < 4; j++) {
                __nv_bfloat16 hb = __float2bfloat16(f[j]);
                float hf = __bfloat162float(hb);
                VtHi[(dg + j) * VT_STRIDE + key] = hb;
                VtLo[(dg + j) * VT_STRIDE + key] = __float2bfloat16(f[j] - hf);
            }
        }
        // ---- gate/mask additive terms ----
        if (tid < BK) {
            float g = __logf(fmaxf(gb[k0 + tid], 1e-6f));
            gsm[tid] = (mb[k0 + tid] == 0) ? -1e30f : g;
        }
        __syncthreads();

        // ---- S = Q K^T (tf32 MMA) ----
        float sacc[8][4];
        #pragma unroll
        for (int nb = 0; nb < 8; nb++) {
            #pragma unroll
            for (int i = 0; i < 4; i++) sacc[nb][i] = 0.0f;
            #pragma unroll
            for (int kb = 0; kb < 8; kb++) {
                uint32_t b0 = Ks[(8 * nb + qr) * KS_STRIDE + 8 * kb + qc];
                uint32_t b1 = Ks[(8 * nb + qr) * KS_STRIDE + 8 * kb + qc + 4];
                mma_tf32(sacc[nb], qa[kb], b0, b1);
            }
        }

        // ---- gate + mask, row max ----
        float mxa = -1e30f, mxb = -1e30f;
        #pragma unroll
        for (int nb = 0; nb < 8; nb++) {
            float g0 = gsm[8 * nb + 2 * qc];
            float g1 = gsm[8 * nb + 2 * qc + 1];
            sacc[nb][0] += g0; sacc[nb][1] += g1;
            sacc[nb][2] += g0; sacc[nb][3] += g1;
            mxa = fmaxf(mxa, fmaxf(sacc[nb][0], sacc[nb][1]));
            mxb = fmaxf(mxb, fmaxf(sacc[nb][2], sacc[nb][3]));
        }
        mxa = fmaxf(mxa, __shfl_xor_sync(0xffffffffu, mxa, 1));
        mxa = fmaxf(mxa, __shfl_xor_sync(0xffffffffu, mxa, 2));
        mxb = fmaxf(mxb, __shfl_xor_sync(0xffffffffu, mxb, 1));
        mxb = fmaxf(mxb, __shfl_xor_sync(0xffffffffu, mxb, 2));

        float mna = fmaxf(m_a, mxa), mnb = fmaxf(m_b, mxb);
        float alpha_a = __expf(m_a - mna), alpha_b = __expf(m_b - mnb);
        m_a = mna; m_b = mnb;

        // ---- exp + row sum ----
        float suma = 0.0f, sumb = 0.0f;
        #pragma unroll
        for (int nb = 0; nb < 8; nb++) {
            sacc[nb][0] = __expf(sacc[nb][0] - m_a);
            sacc[nb][1] = __expf(sacc[nb][1] - m_a);
            sacc[nb][2] = __expf(sacc[nb][2] - m_b);
            sacc[nb][3] = __expf(sacc[nb][3] - m_b);
            suma += sacc[nb][0] + sacc[nb][1];
            sumb += sacc[nb][2] + sacc[nb][3];
        }
        suma += __shfl_xor_sync(0xffffffffu, suma, 1);
        suma += __shfl_xor_sync(0xffffffffu, suma, 2);
        sumb += __shfl_xor_sync(0xffffffffu, sumb, 1);
        sumb += __shfl_xor_sync(0xffffffffu, sumb, 2);
        l_a = l_a * alpha_a + suma;
        l_b = l_b * alpha_b + sumb;

        // ---- rescale O ----
        #pragma unroll
        for (int nb = 0; nb < 8; nb++) {
            oacc[nb][0] *= alpha_a; oacc[nb][1] *= alpha_a;
            oacc[nb][2] *= alpha_b; oacc[nb][3] *= alpha_b;
        }

        // ---- P -> bf16 hi/lo A-fragments (pure register shuffle of S layout) ----
        uint32_t phi[4][4], plo[4][4];
        #pragma unroll
        for (int kb = 0; kb < 4; kb++) {
            pack_bf16_hilo(sacc[2 * kb][0],     sacc[2 * kb][1],     phi[kb][0], plo[kb][0]);
            pack_bf16_hilo(sacc[2 * kb][2],     sacc[2 * kb][3],     phi[kb][1], plo[kb][1]);
            pack_bf16_hilo(sacc[2 * kb + 1][0], sacc[2 * kb + 1][1], phi[kb][2], plo[kb][2]);
            pack_bf16_hilo(sacc[2 * kb + 1][2], sacc[2 * kb + 1][3], phi[kb][3], plo[kb][3]);
        }

        // ---- O += P V (bf16 MMA, 3-term hi/lo) ----
        const uint32_t* VH = (const uint32_t*)VtHi;
        const uint32_t* VL = (const uint32_t*)VtLo;
        #pragma unroll
        for (int nb = 0; nb < 8; nb++) {
            #pragma unroll
            for (int kb = 0; kb < 4; kb++) {
                int off = (8 * nb + qr) * (VT_STRIDE / 2) + 8 * kb + qc;
                uint32_t vh0 = VH[off], vh1 = VH[off + 4];
                uint32_t vl0 = VL[off], vl1 = VL[off + 4];
                mma_bf16(oacc[nb], phi[kb], vh0, vh1);
                mma_bf16(oacc[nb], plo[kb], vh0, vh1);
                mma_bf16(oacc[nb], phi[kb], vl0, vl1);
            }
        }
        __syncthreads();
    }

    // ---- epilogue ----
    float inva = 1.0f / l_a, invb = 1.0f / l_b;
    float* Ob = g_AO + ((size_t)b * LQn + q0 + r0 + qr) * DM + h * DH;
    #pragma unroll
    for (int nb = 0; nb < 8; nb++) {
        float2 va = make_float2(oacc[nb][0] * inva, oacc[nb][1] * inva);
        *(float2*)(Ob + 8 * nb + 2 * qc) = va;
        float2 vb2 = make_float2(oacc[nb][2] * invb, oacc[nb][3] * invb);
        *(float2*)(Ob + (size_t)8 * DM + 8 * nb + 2 * qc) = vb2;
    }
}

extern "C" void kernel_launch(void* const* d_in, const int* in_sizes, int n_in,
                              void* d_out, int out_size) {
    const float* q    = (const float*)d_in[0];
    const float* kv   = (const float*)d_in[1];
    const float* gate = (const float*)d_in[2];
    const int*   mask = (const int*)d_in[3];
    const float* Wq   = (const float*)d_in[4];
    const float* bq   = (const float*)d_in[5];
    const float* Wk   = (const float*)d_in[6];
    const float* bk   = (const float*)d_in[7];
    const float* Wv   = (const float*)d_in[8];
    const float* bv   = (const float*)d_in[9];
    const float* Wo   = (const float*)d_in[10];
    const float* bo   = (const float*)d_in[11];
    float* out = (float*)d_out;

    float *Qp, *Kp, *Vp, *AO;
    cudaGetSymbolAddress((void**)&Qp, g_Qp);
    cudaGetSymbolAddress((void**)&Kp, g_Kp);
    cudaGetSymbolAddress((void**)&Vp, g_Vp);
    cudaGetSymbolAddress((void**)&AO, g_AO);

    dim3 thr(256);
    // Projections
    gemm_bias_kernel<<<dim3(DM / 64, (BSZ * LQn) / 64), thr>>>(q,  Wq, bq, Qp, BSZ * LQn, DM, DM);
    gemm_bias_kernel<<<dim3(DM / 64, (BSZ * LKn) / 64), thr>>>(kv, Wk, bk, Kp, BSZ * LKn, DM, DM);
    gemm_bias_kernel<<<dim3(DM / 64, (BSZ * LKn) / 64), thr>>>(kv, Wv, bv, Vp, BSZ * LKn, DM, DM);
    // Attention (tensor cores)
    attn_kernel<<<dim3(LQn / BQ, NH, BSZ), 128>>>(gate, mask);
    // Output projection
    gemm_bias_kernel<<<dim3(DM / 64, (BSZ * LQn) / 64), thr>>>(AO, Wo, bo, out, BSZ * LQn, DM, DM);
}

// round 9
// speedup vs baseline: 4.0454x; 2.3018x over previous
#include <cuda_runtime.h>
#include <cuda_bf16.h>
#include <math.h>
#include <stdint.h>

#define DM 512
#define NH 8
#define DH 64
#define LQn 2048
#define LKn 4096
#define BSZ 2

#define BQ 64
#define BK 64

// Scratch (allocation-free): projected Q/K/V and attention output, all fp32.
__device__ float g_Qp[(size_t)BSZ * LQn * DM];   // [B*LQ, DM]
__device__ float g_Kp[(size_t)BSZ * LKn * DM];   // [B*LK, DM]
__device__ float g_Vp[(size_t)BSZ * LKn * DM];   // [B*LK, DM]
__device__ float g_AO[(size_t)BSZ * LQn * DM];   // [B*LQ, DM] attention out (heads concat)

// ---------------------------------------------------------------------------
// MMA + packing primitives
// ---------------------------------------------------------------------------
__device__ __forceinline__ void mma_tf32(float c[4], const uint32_t a[4],
                                         uint32_t b0, uint32_t b1) {
    asm volatile(
        "mma.sync.aligned.m16n8k8.row.col.f32.tf32.tf32.f32 "
        "{%0,%1,%2,%3}, {%4,%5,%6,%7}, {%8,%9}, {%0,%1,%2,%3};"
        : "+f"(c[0]), "+f"(c[1]), "+f"(c[2]), "+f"(c[3])
        : "r"(a[0]), "r"(a[1]), "r"(a[2]), "r"(a[3]), "r"(b0), "r"(b1));
}

__device__ __forceinline__ void mma_bf16(float c[4], const uint32_t a[4],
                                         uint32_t b0, uint32_t b1) {
    asm volatile(
        "mma.sync.aligned.m16n8k16.row.col.f32.bf16.bf16.f32 "
        "{%0,%1,%2,%3}, {%4,%5,%6,%7}, {%8,%9}, {%0,%1,%2,%3};"
        : "+f"(c[0]), "+f"(c[1]), "+f"(c[2]), "+f"(c[3])
        : "r"(a[0]), "r"(a[1]), "r"(a[2]), "r"(a[3]), "r"(b0), "r"(b1));
}

__device__ __forceinline__ uint32_t cvt_tf32(float f) {
    uint32_t u;
    asm("cvt.rna.tf32.f32 %0, %1;" : "=r"(u) : "f"(f));
    return u;
}

// pack (f0 -> low half, f1 -> high half) as bf16x2, plus bf16x2 of residuals
__device__ __forceinline__ void pack_bf16_hilo(float f0, float f1,
                                               uint32_t& hi, uint32_t& lo) {
    asm("cvt.rn.bf16x2.f32 %0, %1, %2;" : "=r"(hi) : "f"(f1), "f"(f0));
    float h0 = __uint_as_float(hi << 16);
    float h1 = __uint_as_float(hi & 0xffff0000u);
    float r0 = f0 - h0, r1 = f1 - h1;
    asm("cvt.rn.bf16x2.f32 %0, %1, %2;" : "=r"(lo) : "f"(r1), "f"(r0));
}

__device__ __forceinline__ uint32_t pack_bf16x2(float f0, float f1) {
    uint32_t u;
    asm("cvt.rn.bf16x2.f32 %0, %1, %2;" : "=r"(u) : "f"(f1), "f"(f0));
    return u;
}

// ---------------------------------------------------------------------------
// Tensor-core GEMM: C[M,512] = A[M,512] @ W[512,512]^T + bias
// bf16 3-term hi/lo split (fp32-grade accuracy, ~2^-17 rel error).
// CTA: 128 threads / 4 warps; tile 64x64; warp = 16 rows x 64 cols.
// ---------------------------------------------------------------------------
#define GS 20   // uint32 stride of packed-k rows (16 used + 4 pad) -> conflict-free

__global__ __launch_bounds__(128)
void gemm_bf16_kernel(const float* __restrict__ A,
                      const float* __restrict__ W,
                      const float* __restrict__ bias,
                      float* __restrict__ C, int M) {
    __shared__ uint32_t AsH[64 * GS], AsL[64 * GS];
    __shared__ uint32_t WsH[64 * GS], WsL[64 * GS];

    const int tid = threadIdx.x;
    const int lane = tid & 31, warp = tid >> 5;
    const int qr = lane >> 2, qc = lane & 3;
    const int n0 = blockIdx.x * 64, m0 = blockIdx.y * 64;

    float acc[8][4];
    #pragma unroll
    for (int nb = 0; nb < 8; nb++)
        #pragma unroll
        for (int i = 0; i < 4; i++) acc[nb][i] = 0.0f;

    for (int k0 = 0; k0 < DM; k0 += 32) {
        __syncthreads();
        // Producer: stage A and W k-slab as packed bf16x2 hi/lo
        #pragma unroll
        for (int p = 0; p < 4; p++) {
            int idx = tid + p * 128;
            int r = idx >> 3, fg = idx & 7;
            float4 av = *(const float4*)(A + (size_t)(m0 + r) * DM + k0 + fg * 4);
            uint32_t h0, l0, h1, l1;
            pack_bf16_hilo(av.x, av.y, h0, l0);
            pack_bf16_hilo(av.z, av.w, h1, l1);
            AsH[r * GS + fg * 2] = h0; AsH[r * GS + fg * 2 + 1] = h1;
            AsL[r * GS + fg * 2] = l0; AsL[r * GS + fg * 2 + 1] = l1;
            float4 wv = *(const float4*)(W + (size_t)(n0 + r) * DM + k0 + fg * 4);
            pack_bf16_hilo(wv.x, wv.y, h0, l0);
            pack_bf16_hilo(wv.z, wv.w, h1, l1);
            WsH[r * GS + fg * 2] = h0; WsH[r * GS + fg * 2 + 1] = h1;
            WsL[r * GS + fg * 2] = l0; WsL[r * GS + fg * 2 + 1] = l1;
        }
        __syncthreads();

        // A fragments (2 k16 blocks)
        uint32_t ahH[2][4], ahL[2][4];
        #pragma unroll
        for (int kb = 0; kb < 2; kb++) {
            int base = (16 * warp + qr) * GS + kb * 8 + qc;
            ahH[kb][0] = AsH[base];            ahH[kb][1] = AsH[base + 8 * GS];
            ahH[kb][2] = AsH[base + 4];        ahH[kb][3] = AsH[base + 8 * GS + 4];
            ahL[kb][0] = AsL[base];            ahL[kb][1] = AsL[base + 8 * GS];
            ahL[kb][2] = AsL[base + 4];        ahL[kb][3] = AsL[base + 8 * GS + 4];
        }

        #pragma unroll
        for (int nb = 0; nb < 8; nb++) {
            #pragma unroll
            for (int kb = 0; kb < 2; kb++) {
                int wb = (8 * nb + qr) * GS + kb * 8 + qc;
                uint32_t bh0 = WsH[wb], bh1 = WsH[wb + 4];
                uint32_t bl0 = WsL[wb], bl1 = WsL[wb + 4];
                mma_bf16(acc[nb], ahH[kb], bh0, bh1);
                mma_bf16(acc[nb], ahL[kb], bh0, bh1);
                mma_bf16(acc[nb], ahH[kb], bl0, bl1);
            }
        }
    }

    // Epilogue: + bias, fp32 stores
    const int row0 = m0 + 16 * warp + qr;
    #pragma unroll
    for (int nb = 0; nb < 8; nb++) {
        int n = n0 + 8 * nb + 2 * qc;
        float2 bv = *(const float2*)(bias + n);
        float2 c01 = make_float2(acc[nb][0] + bv.x, acc[nb][1] + bv.y);
        float2 c23 = make_float2(acc[nb][2] + bv.x, acc[nb][3] + bv.y);
        *(float2*)(C + (size_t)row0 * DM + n) = c01;
        *(float2*)(C + (size_t)(row0 + 8) * DM + n) = c23;
    }
}

// ---------------------------------------------------------------------------
// Tensor-core flash attention.
//   S = Q K^T : tf32 MMA (scale folded into Q; gate+mask added after)
//   P V      : bf16 MMA (single term; error ~5e-5 in norm, within budget)
// ---------------------------------------------------------------------------
#define KS_STRIDE 68           // fp32 words per row (64 + 4 pad) -> conflict-free
#define VT_STRIDE 72           // bf16 elems per row (64 + 8 pad) -> conflict-free

__global__ __launch_bounds__(128, 2)
void attn_kernel(const float* __restrict__ gate, const int* __restrict__ mask) {
    __shared__ uint32_t Ks[BK * KS_STRIDE];              // K tile, tf32 bits (also Q staging)
    __shared__ __nv_bfloat16 VtHi[DH * VT_STRIDE];       // V^T bf16, [d][key]
    __shared__ float gsm[BK];

    const int tid = threadIdx.x;
    const int lane = tid & 31, warp = tid >> 5;
    const int qr = lane >> 2;       // 0..7
    const int qc = lane & 3;        // 0..3
    const int r0 = warp * 16;

    const int q0 = blockIdx.x * BQ;
    const int h = blockIdx.y, b = blockIdx.z;

    const float* Qb = g_Qp + ((size_t)b * LQn + q0) * DM + h * DH;
    const float* Kb = g_Kp + (size_t)b * LKn * DM + h * DH;
    const float* Vb = g_Vp + (size_t)b * LKn * DM + h * DH;
    const float* gb = gate + (size_t)b * LKn;
    const int*   mb = mask + (size_t)b * LKn;

    // ---- Stage Q tile (scaled by 1/8, tf32-rounded), extract A frags ----
    #pragma unroll
    for (int p = 0; p < 8; p++) {
        int idx = tid + p * 128;
        int r = idx >> 4, cg = (idx & 15) << 2;
        float4 v = *(const float4*)(Qb + (size_t)r * DM + cg);
        uint4 u;
        u.x = cvt_tf32(v.x * 0.125f);
        u.y = cvt_tf32(v.y * 0.125f);
        u.z = cvt_tf32(v.z * 0.125f);
        u.w = cvt_tf32(v.w * 0.125f);
        *(uint4*)&Ks[r * KS_STRIDE + cg] = u;
    }
    __syncthreads();

    uint32_t qa[8][4];   // Q A-fragments, persistent
    #pragma unroll
    for (int kb = 0; kb < 8; kb++) {
        qa[kb][0] = Ks[(r0 + qr) * KS_STRIDE + 8 * kb + qc];
        qa[kb][1] = Ks[(r0 + qr + 8) * KS_STRIDE + 8 * kb + qc];
        qa[kb][2] = Ks[(r0 + qr) * KS_STRIDE + 8 * kb + qc + 4];
        qa[kb][3] = Ks[(r0 + qr + 8) * KS_STRIDE + 8 * kb + qc + 4];
    }
    __syncthreads();

    float m_a = -1e30f, m_b = -1e30f, l_a = 0.0f, l_b = 0.0f;
    float oacc[8][4];
    #pragma unroll
    for (int nb = 0; nb < 8; nb++)
        #pragma unroll
        for (int i = 0; i < 4; i++) oacc[nb][i] = 0.0f;

    for (int k0 = 0; k0 < LKn; k0 += BK) {
        // ---- K tile -> tf32 ----
        #pragma unroll
        for (int p = 0; p < 8; p++) {
            int idx = tid + p * 128;
            int r = idx >> 4, cg = (idx & 15) << 2;
            float4 v = *(const float4*)(Kb + (size_t)(k0 + r) * DM + cg);
            uint4 u;
            u.x = cvt_tf32(v.x); u.y = cvt_tf32(v.y);
            u.z = cvt_tf32(v.z); u.w = cvt_tf32(v.w);
            *(uint4*)&Ks[r * KS_STRIDE + cg] = u;
        }
        // ---- V tile, transpose to [d][key], bf16 ----
        #pragma unroll
        for (int p = 0; p < 8; p++) {
            int idx = tid + p * 128;
            int key = idx >> 4, dg = (idx & 15) << 2;
            float4 v = *(const float4*)(Vb + (size_t)(k0 + key) * DM + dg);
            VtHi[(dg + 0) * VT_STRIDE + key] = __float2bfloat16(v.x);
            VtHi[(dg + 1) * VT_STRIDE + key] = __float2bfloat16(v.y);
            VtHi[(dg + 2) * VT_STRIDE + key] = __float2bfloat16(v.z);
            VtHi[(dg + 3) * VT_STRIDE + key] = __float2bfloat16(v.w);
        }
        // ---- gate/mask additive terms ----
        if (tid < BK) {
            float g = __logf(fmaxf(gb[k0 + tid], 1e-6f));
            gsm[tid] = (mb[k0 + tid] == 0) ? -1e30f : g;
        }
        __syncthreads();

        // ---- S = Q K^T (tf32 MMA) ----
        float sacc[8][4];
        #pragma unroll
        for (int nb = 0; nb < 8; nb++) {
            #pragma unroll
            for (int i = 0; i < 4; i++) sacc[nb][i] = 0.0f;
            #pragma unroll
            for (int kb = 0; kb < 8; kb++) {
                uint32_t b0 = Ks[(8 * nb + qr) * KS_STRIDE + 8 * kb + qc];
                uint32_t b1 = Ks[(8 * nb + qr) * KS_STRIDE + 8 * kb + qc + 4];
                mma_tf32(sacc[nb], qa[kb], b0, b1);
            }
        }

        // ---- gate + mask, row max ----
        float mxa = -1e30f, mxb = -1e30f;
        #pragma unroll
        for (int nb = 0; nb < 8; nb++) {
            float g0 = gsm[8 * nb + 2 * qc];
            float g1 = gsm[8 * nb + 2 * qc + 1];
            sacc[nb][0] += g0; sacc[nb][1] += g1;
            sacc[nb][2] += g0; sacc[nb][3] += g1;
            mxa = fmaxf(mxa, fmaxf(sacc[nb][0], sacc[nb][1]));
            mxb = fmaxf(mxb, fmaxf(sacc[nb][2], sacc[nb][3]));
        }
        mxa = fmaxf(mxa, __shfl_xor_sync(0xffffffffu, mxa, 1));
        mxa = fmaxf(mxa, __shfl_xor_sync(0xffffffffu, mxa, 2));
        mxb = fmaxf(mxb, __shfl_xor_sync(0xffffffffu, mxb, 1));
        mxb = fmaxf(mxb, __shfl_xor_sync(0xffffffffu, mxb, 2));

        float mna = fmaxf(m_a, mxa), mnb = fmaxf(m_b, mxb);
        float alpha_a = __expf(m_a - mna), alpha_b = __expf(m_b - mnb);
        m_a = mna; m_b = mnb;

        // ---- exp + row sum ----
        float suma = 0.0f, sumb = 0.0f;
        #pragma unroll
        for (int nb = 0; nb < 8; nb++) {
            sacc[nb][0] = __expf(sacc[nb][0] - m_a);
            sacc[nb][1] = __expf(sacc[nb][1] - m_a);
            sacc[nb][2] = __expf(sacc[nb][2] - m_b);
            sacc[nb][3] = __expf(sacc[nb][3] - m_b);
            suma += sacc[nb][0] + sacc[nb][1];
            sumb += sacc[nb][2] + sacc[nb][3];
        }
        suma += __shfl_xor_sync(0xffffffffu, suma, 1);
        suma += __shfl_xor_sync(0xffffffffu, suma, 2);
        sumb += __shfl_xor_sync(0xffffffffu, sumb, 1);
        sumb += __shfl_xor_sync(0xffffffffu, sumb, 2);
        l_a = l_a * alpha_a + suma;
        l_b = l_b * alpha_b + sumb;

        // ---- rescale O ----
        #pragma unroll
        for (int nb = 0; nb < 8; nb++) {
            oacc[nb][0] *= alpha_a; oacc[nb][1] *= alpha_a;
            oacc[nb][2] *= alpha_b; oacc[nb][3] *= alpha_b;
        }

        // ---- P -> bf16 A-fragments (register-only relayout) ----
        uint32_t phi[4][4];
        #pragma unroll
        for (int kb = 0; kb < 4; kb++) {
            phi[kb][0] = pack_bf16x2(sacc[2 * kb][0],     sacc[2 * kb][1]);
            phi[kb][1] = pack_bf16x2(sacc[2 * kb][2],     sacc[2 * kb][3]);
            phi[kb][2] = pack_bf16x2(sacc[2 * kb + 1][0], sacc[2 * kb + 1][1]);
            phi[kb][3] = pack_bf16x2(sacc[2 * kb + 1][2], sacc[2 * kb + 1][3]);
        }

        // ---- O += P V (bf16 MMA) ----
        const uint32_t* VH = (const uint32_t*)VtHi;
        #pragma unroll
        for (int nb = 0; nb < 8; nb++) {
            #pragma unroll
            for (int kb = 0; kb < 4; kb++) {
                int off = (8 * nb + qr) * (VT_STRIDE / 2) + 8 * kb + qc;
                uint32_t vh0 = VH[off], vh1 = VH[off + 4];
                mma_bf16(oacc[nb], phi[kb], vh0, vh1);
            }
        }
        __syncthreads();
    }

    // ---- epilogue ----
    float inva = 1.0f / l_a, invb = 1.0f / l_b;
    float* Ob = g_AO + ((size_t)b * LQn + q0 + r0 + qr) * DM + h * DH;
    #pragma unroll
    for (int nb = 0; nb < 8; nb++) {
        float2 va = make_float2(oacc[nb][0] * inva, oacc[nb][1] * inva);
        *(float2*)(Ob + 8 * nb + 2 * qc) = va;
        float2 vb2 = make_float2(oacc[nb][2] * invb, oacc[nb][3] * invb);
        *(float2*)(Ob + (size_t)8 * DM + 8 * nb + 2 * qc) = vb2;
    }
}

extern "C" void kernel_launch(void* const* d_in, const int* in_sizes, int n_in,
                              void* d_out, int out_size) {
    const float* q    = (const float*)d_in[0];
    const float* kv   = (const float*)d_in[1];
    const float* gate = (const float*)d_in[2];
    const int*   mask = (const int*)d_in[3];
    const float* Wq   = (const float*)d_in[4];
    const float* bq   = (const float*)d_in[5];
    const float* Wk   = (const float*)d_in[6];
    const float* bk   = (const float*)d_in[7];
    const float* Wv   = (const float*)d_in[8];
    const float* bv   = (const float*)d_in[9];
    const float* Wo   = (const float*)d_in[10];
    const float* bo   = (const float*)d_in[11];
    float* out = (float*)d_out;

    float *Qp, *Kp, *Vp, *AO;
    cudaGetSymbolAddress((void**)&Qp, g_Qp);
    cudaGetSymbolAddress((void**)&Kp, g_Kp);
    cudaGetSymbolAddress((void**)&Vp, g_Vp);
    cudaGetSymbolAddress((void**)&AO, g_AO);

    // Projections (tensor-core bf16-split GEMMs)
    gemm_bf16_kernel<<<dim3(DM / 64, (BSZ * LQn) / 64), 128>>>(q,  Wq, bq, Qp, BSZ * LQn);
    gemm_bf16_kernel<<<dim3(DM / 64, (BSZ * LKn) / 64), 128>>>(kv, Wk, bk, Kp, BSZ * LKn);
    gemm_bf16_kernel<<<dim3(DM / 64, (BSZ * LKn) / 64), 128>>>(kv, Wv, bv, Vp, BSZ * LKn);
    // Attention (tensor cores)
    attn_kernel<<<dim3(LQn / BQ, NH, BSZ), 128>>>(gate, mask);
    // Output projection
    gemm_bf16_kernel<<<dim3(DM / 64, (BSZ * LQn) / 64), 128>>>(AO, Wo, bo, out, BSZ * LQn);
}